// round 15
// baseline (speedup 1.0000x reference)
#include <cuda_runtime.h>
#include <math.h>

#define HW   96
#define NB   4
#define NT0  4
#define NT1  8
#define ZT   32
#define CIN  128          // NT0*ZT
#define TW   4
#define TH   4
#define PIXW (TW+4)       // 8
#define PIXH (TH+4)       // 8
#define NPIX (PIXW*PIXH)  // 64
#define PSTRIDE 140       // per-pixel smem stride in floats (4 groups of 32 + 4 pad each)
#define NTHR 256
// s_out layout: [pix*292 + T*36 + z]
#define OPIX 292
#define OT   36

// transposed input scratch: [n][h][w][c], c = i*32 + z
__device__ float g_xt[NB*HW*HW*CIN];

// ---------------- Kernel A: (N,T0,Z,H,W) -> (N,H,W,C) transpose ----------------
__global__ __launch_bounds__(256) void k_transpose(const float* __restrict__ in)
{
    __shared__ float tile[32][33];
    int wt = blockIdx.x;          // 0..2  (w tile of 32)
    int h  = blockIdx.y;          // 0..95
    int ni = blockIdx.z;          // 0..15 = n*4+i
    int n = ni >> 2, i = ni & 3;
    int tx = threadIdx.x, ty = threadIdx.y;
    int w0 = wt * 32;
    #pragma unroll
    for (int k = 0; k < 4; k++) {
        int z = ty + 8*k;
        tile[z][tx] = in[(((n*NT0 + i)*ZT + z)*HW + h)*HW + w0 + tx];
    }
    __syncthreads();
    #pragma unroll
    for (int k = 0; k < 4; k++) {
        int w = w0 + ty + 8*k;
        g_xt[((n*HW + h)*HW + w)*CIN + i*32 + tx] = tile[tx][ty + 8*k];
    }
}

// ---------------- packed f32x2 helpers ----------------
__device__ __forceinline__ unsigned long long pack2(float x, float y) {
    unsigned long long r;
    asm("mov.b64 %0, {%1,%2};" : "=l"(r) : "f"(x), "f"(y));
    return r;
}
__device__ __forceinline__ void fma2(unsigned long long& d, unsigned long long a, unsigned long long b) {
    asm("fma.rn.f32x2 %0, %1, %2, %3;" : "=l"(d) : "l"(a), "l"(b), "l"(d));
}
__device__ __forceinline__ void unpack2(unsigned long long v, float& lo, float& hi) {
    asm("mov.b64 {%0,%1}, %2;" : "=f"(lo), "=f"(hi) : "l"(v));
}

// ---------------- Kernel B: fused conv + capsule transform + routing ----------------
__global__ __launch_bounds__(NTHR, 3) void k_caps(
    const float* __restrict__ Wc,   // (T0,5,5,1,T1) = 800
    const float* __restrict__ Wp,   // (T0,16,T1)    = 512
    const float* __restrict__ Wa,   // (T0,16,T1)    = 512
    const float* __restrict__ Ba,   // (T0,T1)       = 32
    float* __restrict__ out)        // (N,8,32,H,W)
{
    __shared__ __align__(16) float s_in[NPIX*PSTRIDE]; // 8960 floats; reused as s_out
    __shared__ float2 s_wcp[400];         // [(o*4+ta)*25 + k] = (Wc[o,k,ta], Wc[o,k,ta+4])
    __shared__ float s_mp[32*17];         // [o*8+T][r*4+c] normalized W_pos
    __shared__ float s_ma[32*17];         // [o*8+T][r*4+c] W_app
    __shared__ float s_ba[32];            // [o*8+T]

    const int tid = threadIdx.x;
    const int n  = blockIdx.z;
    const int h0 = blockIdx.y * TH;
    const int w0 = blockIdx.x * TW;

    // ---- stage params ----  m[T][r][c] = Wp[i*128 + T*16 + r*4 + c]
    #pragma unroll
    for (int k = 0; k < 2; k++) {
        int idx = tid + NTHR*k;
        int i = idx >> 7, T = (idx >> 4) & 7, rc = idx & 15;
        s_mp[(i*8 + T)*17 + rc] = Wp[idx];
        s_ma[(i*8 + T)*17 + rc] = Wa[idx];
    }
    #pragma unroll
    for (int k = 0; k < 2; k++) {
        int idx = tid + NTHR*k;
        if (idx < 400) {
            int o = idx / 100, rem = idx - o*100;
            int ta = rem / 25, kk = rem - ta*25;
            s_wcp[idx] = make_float2(Wc[o*200 + kk*8 + ta], Wc[o*200 + kk*8 + ta + 4]);
        }
    }
    if (tid < 32)  s_ba[tid] = Ba[tid];

    // ---- stage input tile (halo 2, zero pad OOB), float4 ----
    #pragma unroll
    for (int k = 0; k < 8; k++) {
        int L = tid + NTHR*k;           // 64*32 = 2048 float4 total
        int pix = L >> 5, c4 = L & 31;
        int c = c4 << 2;
        int py = pix >> 3, px = pix & 7;
        int gh = h0 - 2 + py, gw = w0 - 2 + px;
        float4 v = make_float4(0.f, 0.f, 0.f, 0.f);
        if (gh >= 0 && gh < HW && gw >= 0 && gw < HW)
            v = *reinterpret_cast<const float4*>(&g_xt[((n*HW + gh)*HW + gw)*CIN + c]);
        *reinterpret_cast<float4*>(&s_in[pix*PSTRIDE + c + ((c >> 5) << 2)]) = v;
    }
    __syncthreads();

    // ---- normalize W_pos columns ----
    if (tid < 128) {
        int i = tid >> 5, T = (tid >> 2) & 7, cc = tid & 3;
        int base = (i*8 + T)*17;
        float s = 0.f;
        #pragma unroll
        for (int r = 0; r < 4; r++) { float v = s_mp[base + r*4 + cc]; s += v*v; }
        float inv = 1.f / sqrtf(fmaxf(s, 1e-12f));
        #pragma unroll
        for (int r = 0; r < 4; r++) s_mp[base + r*4 + cc] *= inv;
    }
    __syncthreads();

    // ---- per-warp pixel column, 2 output rows per lane ----
    const int warp = tid >> 5, lane = tid & 31;
    const int wy = warp >> 2, px = warp & 3;
    const int py0 = wy * 2;
    const int o = lane >> 3,  T = lane & 7;
    const int ta = T >> 1;
    const int zlo = (T & 1) << 4;
    const int wbase = (o*4 + ta)*25;

    unsigned long long aP0[8], aA0[8], aP1[8], aA1[8];
    #pragma unroll
    for (int j = 0; j < 8; j++) { aP0[j]=0ull; aA0[j]=0ull; aP1[j]=0ull; aA1[j]=0ull; }

    // input rows py0..py0+5 loaded once; row0 uses weight row j, row1 uses j-1
    #pragma unroll
    for (int j = 0; j < 6; j++) {
        #pragma unroll
        for (int kx = 0; kx < 5; kx++) {
            const ulonglong2* pin = reinterpret_cast<const ulonglong2*>(
                s_in + ((py0 + j)*PIXW + (px + kx))*PSTRIDE + o*36 + zlo);
            unsigned long long wa0=0ull, wb0=0ull, wa1=0ull, wb1=0ull;
            if (j < 5) {
                float2 w = s_wcp[wbase + j*5 + kx];
                wa0 = pack2(w.x, w.x); wb0 = pack2(w.y, w.y);
            }
            if (j > 0) {
                float2 w = s_wcp[wbase + (j-1)*5 + kx];
                wa1 = pack2(w.x, w.x); wb1 = pack2(w.y, w.y);
            }
            {   // chunk 0: z 0..7 of slice
                ulonglong2 x0 = pin[0];
                ulonglong2 x1 = pin[1];
                if (j < 5) {
                    fma2(aP0[0], x0.x, wa0); fma2(aP0[1], x0.y, wa0);
                    fma2(aP0[2], x1.x, wa0); fma2(aP0[3], x1.y, wa0);
                    fma2(aA0[0], x0.x, wb0); fma2(aA0[1], x0.y, wb0);
                    fma2(aA0[2], x1.x, wb0); fma2(aA0[3], x1.y, wb0);
                }
                if (j > 0) {
                    fma2(aP1[0], x0.x, wa1); fma2(aP1[1], x0.y, wa1);
                    fma2(aP1[2], x1.x, wa1); fma2(aP1[3], x1.y, wa1);
                    fma2(aA1[0], x0.x, wb1); fma2(aA1[1], x0.y, wb1);
                    fma2(aA1[2], x1.x, wb1); fma2(aA1[3], x1.y, wb1);
                }
            }
            {   // chunk 1: z 8..15 of slice
                ulonglong2 x2 = pin[2];
                ulonglong2 x3 = pin[3];
                if (j < 5) {
                    fma2(aP0[4], x2.x, wa0); fma2(aP0[5], x2.y, wa0);
                    fma2(aP0[6], x3.x, wa0); fma2(aP0[7], x3.y, wa0);
                    fma2(aA0[4], x2.x, wb0); fma2(aA0[5], x2.y, wb0);
                    fma2(aA0[6], x3.x, wb0); fma2(aA0[7], x3.y, wb0);
                }
                if (j > 0) {
                    fma2(aP1[4], x2.x, wa1); fma2(aP1[5], x2.y, wa1);
                    fma2(aP1[6], x3.x, wa1); fma2(aP1[7], x3.y, wa1);
                    fma2(aA1[4], x2.x, wb1); fma2(aA1[5], x2.y, wb1);
                    fma2(aA1[6], x3.x, wb1); fma2(aA1[7], x3.y, wb1);
                }
            }
        }
    }

    __syncthreads();                // all warps done reading s_in tile data
    float* s_out = s_in;            // [pix16*OPIX + T*OT + z]

    const bool posl = (o < 2);
    const bool lowh = (o < 2);      // owns z[0,16)
    const bool lowq = ((o & 1) == 0);
    const float xc = (float)(w0 + px) * (1.f/96.f);
    const float bap = s_ba[lane];

    #pragma unroll
    for (int rr = 0; rr < 2; rr++) {
        const int pyr = py0 + rr;
        const float yc = (float)(h0 + pyr) * (1.f/96.f);

        float up[16], ua[16];
        #pragma unroll
        for (int j = 0; j < 8; j++) {
            unpack2(rr == 0 ? aP0[j] : aP1[j], up[2*j], up[2*j+1]);
            unpack2(rr == 0 ? aA0[j] : aA1[j], ua[2*j], ua[2*j+1]);
        }
        #pragma unroll
        for (int q = 0; q < 16; q++) ua[q] += bap;   // app bias in place

        // ---- capsule transform, column-wise M loads (4 live mm regs) ----
        float u[32];
        #pragma unroll
        for (int b = 0; b < 4; b++) {
            float m0 = s_mp[lane*17 + b];
            float m1 = s_mp[lane*17 + 4 + b];
            float m2 = s_mp[lane*17 + 8 + b];
            float m3 = s_mp[lane*17 + 12 + b];
            if (b == 0) m3 += xc;
            if (b == 1) m3 += yc;
            #pragma unroll
            for (int a = 0; a < 4; a++)
                u[a*4+b] = up[4*a]*m0 + up[4*a+1]*m1 + up[4*a+2]*m2 + up[4*a+3]*m3;
        }
        #pragma unroll
        for (int b = 0; b < 4; b++) {
            float m0 = s_ma[lane*17 + b];
            float m1 = s_ma[lane*17 + 4 + b];
            float m2 = s_ma[lane*17 + 8 + b];
            float m3 = s_ma[lane*17 + 12 + b];
            #pragma unroll
            for (int a = 0; a < 4; a++)
                u[16 + a*4 + b] = ua[4*a]*m0 + ua[4*a+1]*m1 + ua[4*a+2]*m2 + ua[4*a+3]*m3;
        }

        // ---- fused warp transpose: columns -> slices (no keepv/othv arrays) ----
        // v_j[k] = u_{col o^j}[o*8 + k]
        float v0[8], v1[8], v2[8], v3[8];
        #pragma unroll
        for (int k = 0; k < 8; k++) {
            float a_own_e1 = lowh ? (lowq ? u[k]      : u[8+k])
                                  : (lowq ? u[16+k]   : u[24+k]);
            float a_own_e2 = lowh ? (lowq ? u[8+k]    : u[k])
                                  : (lowq ? u[24+k]   : u[16+k]);
            float a_oth_e1 = lowh ? (lowq ? u[16+k]   : u[24+k])
                                  : (lowq ? u[k]      : u[8+k]);
            float a_oth_e2 = lowh ? (lowq ? u[24+k]   : u[16+k])
                                  : (lowq ? u[8+k]    : u[k]);
            v0[k] = a_own_e1;
            v1[k] = __shfl_xor_sync(0xffffffffu, a_own_e2, 8);
            v2[k] = __shfl_xor_sync(0xffffffffu, a_oth_e1, 16);
            v3[k] = __shfl_xor_sync(0xffffffffu, a_oth_e2, 24);
        }

        // ---- dynamic routing ----
        float blog = 0.f, sp = 0.f, sa = 0.f;
        float pl[8];
        #pragma unroll
        for (int it = 0; it < 3; it++) {
            float r = 1.f / (1.f + __expf(-blog));
            float a0 = r;
            float a1 = __shfl_xor_sync(0xffffffffu, r, 8);
            float a2 = __shfl_xor_sync(0xffffffffu, r, 16);
            float a3 = __shfl_xor_sync(0xffffffffu, r, 24);
            #pragma unroll
            for (int k = 0; k < 8; k++)
                pl[k] = v0[k]*a0 + v1[k]*a1 + v2[k]*a2 + v3[k]*a3;
            float mloc = fabsf(pl[0]);
            float nloc = pl[0]*pl[0];
            #pragma unroll
            for (int k = 1; k < 8; k++) {
                mloc = fmaxf(mloc, fabsf(pl[k]));
                nloc = fmaf(pl[k], pl[k], nloc);
            }
            float m2 = fmaxf(mloc, __shfl_xor_sync(0xffffffffu, mloc, 8));
            float s2 = nloc + __shfl_xor_sync(0xffffffffu, nloc, 8);
            float val = posl ? m2 : s2;
            float w_  = __shfl_xor_sync(0xffffffffu, val, 16);
            float mx = posl ? m2 : w_;
            float n2 = posl ? w_ : s2;
            sp = 1.f / mx;
            float nn = sqrtf(n2 + 1e-9f);
            sa = n2 / ((1.f + n2) * nn);
            if (it < 2) {
                float q0 = 0.f, q1 = 0.f, q2 = 0.f, q3 = 0.f;
                #pragma unroll
                for (int k = 0; k < 8; k++) {
                    q0 = fmaf(v0[k], pl[k], q0);
                    q1 = fmaf(v1[k], pl[k], q1);
                    q2 = fmaf(v2[k], pl[k], q2);
                    q3 = fmaf(v3[k], pl[k], q3);
                }
                float Q0 = q0 + __shfl_xor_sync(0xffffffffu, q1, 8);
                float Q2 = q2 + __shfl_xor_sync(0xffffffffu, q3, 8);
                float D0 = __shfl_xor_sync(0xffffffffu, Q2, 16);
                float dp = posl ? Q0 : D0;
                float da = posl ? D0 : Q0;
                blog += (dp * sp) * (da * sa);
            }
        }
        // final v: scale and store 8 floats (z = o*8..o*8+7)
        {
            float scl = posl ? sp : sa;
            int pix16 = pyr*4 + px;
            float4* dst = reinterpret_cast<float4*>(&s_out[pix16*OPIX + T*OT + o*8]);
            dst[0] = make_float4(pl[0]*scl, pl[1]*scl, pl[2]*scl, pl[3]*scl);
            dst[1] = make_float4(pl[4]*scl, pl[5]*scl, pl[6]*scl, pl[7]*scl);
        }
    }
    __syncthreads();

    // ---- output write: out[n][t][z][h][w] (16B runs of w) ----
    #pragma unroll
    for (int k = 0; k < 16; k++) {
        int e = tid + k*NTHR;           // 16 pixels x 256 (t,z)
        int pix = e & 15, tz = e >> 4;
        int t = tz >> 5, z = tz & 31;
        int gh = h0 + (pix >> 2), gw = w0 + (pix & 3);
        out[(((n*8 + t)*32 + z)*HW + gh)*HW + gw] = s_out[pix*OPIX + t*OT + z];
    }
}

extern "C" void kernel_launch(void* const* d_in, const int* in_sizes, int n_in,
                              void* d_out, int out_size)
{
    (void)in_sizes; (void)n_in; (void)out_size;
    const float* x  = (const float*)d_in[0];
    const float* Wc = (const float*)d_in[1];
    const float* Wp = (const float*)d_in[2];
    const float* Wa = (const float*)d_in[3];
    const float* Ba = (const float*)d_in[4];
    float* out = (float*)d_out;

    dim3 gA(3, 96, 16), bA(32, 8);
    k_transpose<<<gA, bA>>>(x);

    dim3 gB(HW/TW, HW/TH, NB);          // (24, 24, 4)
    k_caps<<<gB, NTHR>>>(Wc, Wp, Wa, Ba, out);
}

// round 16
// speedup vs baseline: 1.5937x; 1.5937x over previous
#include <cuda_runtime.h>
#include <math.h>

#define HW   96
#define NB   4
#define NT0  4
#define ZT   32
#define CIN  128
#define TW   4
#define TH   4
#define PIXW (TW+4)       // 8
#define PIXH (TH+4)       // 8
#define NPIX (PIXW*PIXH)  // 64
#define PSTRIDE 140
#define NTHR 256
#define OPIX 292
#define OT   36

// dynamic smem carve (floats)
#define F_IN   0            // 8960
#define F_WCP  8960         // 800 (400 float2)
#define F_MP   9760         // 544
#define F_MA   10304        // 544
#define F_BA   10848        // 32
#define F_SCR  10880        // 8192 (32 x 256)
#define SMEM_FLOATS 19072
#define SMEM_BYTES  (SMEM_FLOATS*4)

__device__ float g_xt[NB*HW*HW*CIN];

// ---------------- Kernel A ----------------
__global__ __launch_bounds__(256) void k_transpose(const float* __restrict__ in)
{
    __shared__ float tile[32][33];
    int wt = blockIdx.x, h = blockIdx.y, ni = blockIdx.z;
    int n = ni >> 2, i = ni & 3;
    int tx = threadIdx.x, ty = threadIdx.y;
    int w0 = wt * 32;
    #pragma unroll
    for (int k = 0; k < 4; k++) {
        int z = ty + 8*k;
        tile[z][tx] = in[(((n*NT0 + i)*ZT + z)*HW + h)*HW + w0 + tx];
    }
    __syncthreads();
    #pragma unroll
    for (int k = 0; k < 4; k++) {
        int w = w0 + ty + 8*k;
        g_xt[((n*HW + h)*HW + w)*CIN + i*32 + tx] = tile[tx][ty + 8*k];
    }
}

// ---------------- packed f32x2 helpers ----------------
__device__ __forceinline__ unsigned long long pack2(float x, float y) {
    unsigned long long r;
    asm("mov.b64 %0, {%1,%2};" : "=l"(r) : "f"(x), "f"(y));
    return r;
}
__device__ __forceinline__ void fma2(unsigned long long& d, unsigned long long a, unsigned long long b) {
    asm("fma.rn.f32x2 %0, %1, %2, %3;" : "=l"(d) : "l"(a), "l"(b), "l"(d));
}
__device__ __forceinline__ void unpack2(unsigned long long v, float& lo, float& hi) {
    asm("mov.b64 {%0,%1}, %2;" : "=f"(lo), "=f"(hi) : "l"(v));
}

// ---------------- Kernel B ----------------
__global__ __launch_bounds__(NTHR, 3) void k_caps(
    const float* __restrict__ Wc,
    const float* __restrict__ Wp,
    const float* __restrict__ Wa,
    const float* __restrict__ Ba,
    float* __restrict__ out)
{
    extern __shared__ __align__(16) float smem[];
    float*  s_in  = smem + F_IN;
    float2* s_wcp = reinterpret_cast<float2*>(smem + F_WCP);
    float*  s_mp  = smem + F_MP;
    float*  s_ma  = smem + F_MA;
    float*  s_ba  = smem + F_BA;
    float*  s_scr = smem + F_SCR;

    const int tid = threadIdx.x;
    const int n  = blockIdx.z;
    const int h0 = blockIdx.y * TH;
    const int w0 = blockIdx.x * TW;

    // ---- stage params ----  m[T][r][c] = Wp[i*128 + T*16 + r*4 + c]
    #pragma unroll
    for (int k = 0; k < 2; k++) {
        int idx = tid + NTHR*k;
        int i = idx >> 7, T = (idx >> 4) & 7, rc = idx & 15;
        s_mp[(i*8 + T)*17 + rc] = Wp[idx];
        s_ma[(i*8 + T)*17 + rc] = Wa[idx];
    }
    #pragma unroll
    for (int k = 0; k < 2; k++) {
        int idx = tid + NTHR*k;
        if (idx < 400) {
            int o = idx / 100, rem = idx - o*100;
            int ta = rem / 25, kk = rem - ta*25;
            s_wcp[idx] = make_float2(Wc[o*200 + kk*8 + ta], Wc[o*200 + kk*8 + ta + 4]);
        }
    }
    if (tid < 32)  s_ba[tid] = Ba[tid];

    // ---- stage input tile (halo 2, zero pad OOB), float4 ----
    #pragma unroll
    for (int k = 0; k < 8; k++) {
        int L = tid + NTHR*k;
        int pix = L >> 5, c4 = L & 31;
        int c = c4 << 2;
        int py = pix >> 3, px = pix & 7;
        int gh = h0 - 2 + py, gw = w0 - 2 + px;
        float4 v = make_float4(0.f, 0.f, 0.f, 0.f);
        if (gh >= 0 && gh < HW && gw >= 0 && gw < HW)
            v = *reinterpret_cast<const float4*>(&g_xt[((n*HW + gh)*HW + gw)*CIN + c]);
        *reinterpret_cast<float4*>(&s_in[pix*PSTRIDE + c + ((c >> 5) << 2)]) = v;
    }
    __syncthreads();

    // ---- normalize W_pos columns ----
    if (tid < 128) {
        int i = tid >> 5, T = (tid >> 2) & 7, cc = tid & 3;
        int base = (i*8 + T)*17;
        float s = 0.f;
        #pragma unroll
        for (int r = 0; r < 4; r++) { float v = s_mp[base + r*4 + cc]; s += v*v; }
        float inv = 1.f / sqrtf(fmaxf(s, 1e-12f));
        #pragma unroll
        for (int r = 0; r < 4; r++) s_mp[base + r*4 + cc] *= inv;
    }
    __syncthreads();

    // ---- lane roles ----
    const int warp = tid >> 5, lane = tid & 31;
    const int wy = warp >> 2, px = warp & 3;
    const int py0 = wy * 2;
    const int o = lane >> 3,  T = lane & 7;
    const int ta = T >> 1;
    const int zlo = (T & 1) << 4;
    const int wbase = (o*4 + ta)*25;
    const float xc  = (float)(w0 + px) * (1.f/96.f);
    const float yc0 = (float)(h0 + py0) * (1.f/96.f);
    const float yc1 = (float)(h0 + py0 + 1) * (1.f/96.f);
    const float bap = s_ba[lane];

    float u0b[16], u1b[16];   // pass-1 (chunk-1) partials, rows 0/1

    // ---- conv in 2 z-chunk passes (16 u64 accs live per pass) ----
    #pragma unroll
    for (int zc = 0; zc < 2; zc++) {
        unsigned long long aP0[4], aA0[4], aP1[4], aA1[4];
        #pragma unroll
        for (int j = 0; j < 4; j++) { aP0[j]=0ull; aA0[j]=0ull; aP1[j]=0ull; aA1[j]=0ull; }

        #pragma unroll
        for (int j = 0; j < 6; j++) {
            #pragma unroll
            for (int kx = 0; kx < 5; kx++) {
                const ulonglong2* pin = reinterpret_cast<const ulonglong2*>(
                    s_in + ((py0 + j)*PIXW + (px + kx))*PSTRIDE + o*36 + zlo) + zc*2;
                ulonglong2 x0 = pin[0];
                ulonglong2 x1 = pin[1];
                if (j < 5) {
                    float2 w = s_wcp[wbase + j*5 + kx];
                    unsigned long long wa = pack2(w.x, w.x);
                    unsigned long long wb = pack2(w.y, w.y);
                    fma2(aP0[0], x0.x, wa); fma2(aP0[1], x0.y, wa);
                    fma2(aP0[2], x1.x, wa); fma2(aP0[3], x1.y, wa);
                    fma2(aA0[0], x0.x, wb); fma2(aA0[1], x0.y, wb);
                    fma2(aA0[2], x1.x, wb); fma2(aA0[3], x1.y, wb);
                }
                if (j > 0) {
                    float2 w = s_wcp[wbase + (j-1)*5 + kx];
                    unsigned long long wa = pack2(w.x, w.x);
                    unsigned long long wb = pack2(w.y, w.y);
                    fma2(aP1[0], x0.x, wa); fma2(aP1[1], x0.y, wa);
                    fma2(aP1[2], x1.x, wa); fma2(aP1[3], x1.y, wa);
                    fma2(aA1[0], x0.x, wb); fma2(aA1[1], x0.y, wb);
                    fma2(aA1[2], x1.x, wb); fma2(aA1[3], x1.y, wb);
                }
            }
        }

        // ---- transform this chunk for both rows (M regs shared) ----
        float up0[8], ua0[8], up1[8], ua1[8];
        #pragma unroll
        for (int j = 0; j < 4; j++) {
            unpack2(aP0[j], up0[2*j], up0[2*j+1]);
            unpack2(aA0[j], ua0[2*j], ua0[2*j+1]);
            unpack2(aP1[j], up1[2*j], up1[2*j+1]);
            unpack2(aA1[j], ua1[2*j], ua1[2*j+1]);
        }
        #pragma unroll
        for (int q = 0; q < 8; q++) { ua0[q] += bap; ua1[q] += bap; }

        float t0[16], t1[16];   // [0..7]=pos u[8zc+..], [8..15]=app u[16+8zc+..]
        #pragma unroll
        for (int b = 0; b < 4; b++) {
            float m0 = s_mp[lane*17 + b];
            float m1 = s_mp[lane*17 + 4 + b];
            float m2 = s_mp[lane*17 + 8 + b];
            float m3 = s_mp[lane*17 + 12 + b];
            float m3r0 = m3, m3r1 = m3;
            if (b == 0) { m3r0 += xc;  m3r1 += xc; }
            if (b == 1) { m3r0 += yc0; m3r1 += yc1; }
            #pragma unroll
            for (int a = 0; a < 2; a++) {
                t0[a*4+b] = up0[4*a]*m0 + up0[4*a+1]*m1 + up0[4*a+2]*m2 + up0[4*a+3]*m3r0;
                t1[a*4+b] = up1[4*a]*m0 + up1[4*a+1]*m1 + up1[4*a+2]*m2 + up1[4*a+3]*m3r1;
            }
        }
        #pragma unroll
        for (int b = 0; b < 4; b++) {
            float m0 = s_ma[lane*17 + b];
            float m1 = s_ma[lane*17 + 4 + b];
            float m2 = s_ma[lane*17 + 8 + b];
            float m3 = s_ma[lane*17 + 12 + b];
            #pragma unroll
            for (int a = 0; a < 2; a++) {
                t0[8 + a*4+b] = ua0[4*a]*m0 + ua0[4*a+1]*m1 + ua0[4*a+2]*m2 + ua0[4*a+3]*m3;
                t1[8 + a*4+b] = ua1[4*a]*m0 + ua1[4*a+1]*m1 + ua1[4*a+2]*m2 + ua1[4*a+3]*m3;
            }
        }

        if (zc == 0) {   // park chunk-0 partials in smem (conflict-free, per-lane column)
            #pragma unroll
            for (int q = 0; q < 16; q++) {
                s_scr[q*256 + tid]      = t0[q];
                s_scr[(16+q)*256 + tid] = t1[q];
            }
        } else {
            #pragma unroll
            for (int q = 0; q < 16; q++) { u0b[q] = t0[q]; u1b[q] = t1[q]; }
        }
    }

    __syncthreads();                // all conv reads of s_in done
    float* s_out = s_in;            // [pix16*OPIX + T*OT + z]

    const bool posl = (o < 2);
    const bool lowh = (o < 2);
    const bool lowq = ((o & 1) == 0);

    #pragma unroll
    for (int rr = 0; rr < 2; rr++) {
        // assemble u[32]: chunk0 from scratch, chunk1 from regs
        float u[32];
        #pragma unroll
        for (int q = 0; q < 8; q++) {
            u[q]      = s_scr[(rr*16 + q)*256 + tid];
            u[16 + q] = s_scr[(rr*16 + 8 + q)*256 + tid];
            u[8 + q]  = (rr == 0) ? u0b[q]     : u1b[q];
            u[24 + q] = (rr == 0) ? u0b[8 + q] : u1b[8 + q];
        }

        // ---- fused warp transpose: columns -> slices ----
        float v0[8], v1[8], v2[8], v3[8];
        #pragma unroll
        for (int k = 0; k < 8; k++) {
            float a_own_e1 = lowh ? (lowq ? u[k]      : u[8+k])
                                  : (lowq ? u[16+k]   : u[24+k]);
            float a_own_e2 = lowh ? (lowq ? u[8+k]    : u[k])
                                  : (lowq ? u[24+k]   : u[16+k]);
            float a_oth_e1 = lowh ? (lowq ? u[16+k]   : u[24+k])
                                  : (lowq ? u[k]      : u[8+k]);
            float a_oth_e2 = lowh ? (lowq ? u[24+k]   : u[16+k])
                                  : (lowq ? u[8+k]    : u[k]);
            v0[k] = a_own_e1;
            v1[k] = __shfl_xor_sync(0xffffffffu, a_own_e2, 8);
            v2[k] = __shfl_xor_sync(0xffffffffu, a_oth_e1, 16);
            v3[k] = __shfl_xor_sync(0xffffffffu, a_oth_e2, 24);
        }

        // ---- dynamic routing ----
        float blog = 0.f, sp = 0.f, sa = 0.f;
        float pl[8];
        #pragma unroll
        for (int it = 0; it < 3; it++) {
            float r = 1.f / (1.f + __expf(-blog));
            float a0 = r;
            float a1 = __shfl_xor_sync(0xffffffffu, r, 8);
            float a2 = __shfl_xor_sync(0xffffffffu, r, 16);
            float a3 = __shfl_xor_sync(0xffffffffu, r, 24);
            #pragma unroll
            for (int k = 0; k < 8; k++)
                pl[k] = v0[k]*a0 + v1[k]*a1 + v2[k]*a2 + v3[k]*a3;
            float mloc = fabsf(pl[0]);
            float nloc = pl[0]*pl[0];
            #pragma unroll
            for (int k = 1; k < 8; k++) {
                mloc = fmaxf(mloc, fabsf(pl[k]));
                nloc = fmaf(pl[k], pl[k], nloc);
            }
            float m2 = fmaxf(mloc, __shfl_xor_sync(0xffffffffu, mloc, 8));
            float s2 = nloc + __shfl_xor_sync(0xffffffffu, nloc, 8);
            float val = posl ? m2 : s2;
            float w_  = __shfl_xor_sync(0xffffffffu, val, 16);
            float mx = posl ? m2 : w_;
            float n2 = posl ? w_ : s2;
            sp = 1.f / mx;
            float nn = sqrtf(n2 + 1e-9f);
            sa = n2 / ((1.f + n2) * nn);
            if (it < 2) {
                float q0 = 0.f, q1 = 0.f, q2 = 0.f, q3 = 0.f;
                #pragma unroll
                for (int k = 0; k < 8; k++) {
                    q0 = fmaf(v0[k], pl[k], q0);
                    q1 = fmaf(v1[k], pl[k], q1);
                    q2 = fmaf(v2[k], pl[k], q2);
                    q3 = fmaf(v3[k], pl[k], q3);
                }
                float Q0 = q0 + __shfl_xor_sync(0xffffffffu, q1, 8);
                float Q2 = q2 + __shfl_xor_sync(0xffffffffu, q3, 8);
                float D0 = __shfl_xor_sync(0xffffffffu, Q2, 16);
                float dp = posl ? Q0 : D0;
                float da = posl ? D0 : Q0;
                blog += (dp * sp) * (da * sa);
            }
        }
        // final v: scale and store 8 floats (z = o*8..o*8+7)
        {
            float scl = posl ? sp : sa;
            int pix16 = (py0 + rr)*4 + px;
            float4* dst = reinterpret_cast<float4*>(&s_out[pix16*OPIX + T*OT + o*8]);
            dst[0] = make_float4(pl[0]*scl, pl[1]*scl, pl[2]*scl, pl[3]*scl);
            dst[1] = make_float4(pl[4]*scl, pl[5]*scl, pl[6]*scl, pl[7]*scl);
        }
    }
    __syncthreads();

    // ---- output write: out[n][t][z][h][w] ----
    #pragma unroll
    for (int k = 0; k < 16; k++) {
        int e = tid + k*NTHR;
        int pix = e & 15, tz = e >> 4;
        int t = tz >> 5, z = tz & 31;
        int gh = h0 + (pix >> 2), gw = w0 + (pix & 3);
        out[(((n*8 + t)*32 + z)*HW + gh)*HW + gw] = s_out[pix*OPIX + t*OT + z];
    }
}

extern "C" void kernel_launch(void* const* d_in, const int* in_sizes, int n_in,
                              void* d_out, int out_size)
{
    (void)in_sizes; (void)n_in; (void)out_size;
    const float* x  = (const float*)d_in[0];
    const float* Wc = (const float*)d_in[1];
    const float* Wp = (const float*)d_in[2];
    const float* Wa = (const float*)d_in[3];
    const float* Ba = (const float*)d_in[4];
    float* out = (float*)d_out;

    cudaFuncSetAttribute(k_caps, cudaFuncAttributeMaxDynamicSharedMemorySize, SMEM_BYTES);

    dim3 gA(3, 96, 16), bA(32, 8);
    k_transpose<<<gA, bA>>>(x);

    dim3 gB(HW/TW, HW/TH, NB);          // (24, 24, 4)
    k_caps<<<gB, NTHR, SMEM_BYTES>>>(Wc, Wp, Wa, Ba, out);
}